// round 1
// baseline (speedup 1.0000x reference)
#include <cuda_runtime.h>
#include <math.h>

#define NB 256
#define NT 10
#define BT 2560
#define NP 49
#define VDIM 512
#define QDIM 128
#define HDIM 256
#define ADIM 128

// vf2 scratch: 2560*49*512 floats (~257 MB). Static device array (no runtime alloc).
static __device__ float g_vf2[(size_t)BT * NP * VDIM];

__device__ __forceinline__ float wsum(float v){
#pragma unroll
    for (int s = 16; s > 0; s >>= 1) v += __shfl_xor_sync(0xffffffffu, v, s);
    return v;
}
__device__ __forceinline__ float wmax(float v){
#pragma unroll
    for (int s = 16; s > 0; s >>= 1) v = fmaxf(v, __shfl_xor_sync(0xffffffffu, v, s));
    return v;
}

// ---------------------------------------------------------------------------
// Kernel 1: per-item visual self-attention + residual + LayerNorm -> g_vf2
// ---------------------------------------------------------------------------
__global__ void __launch_bounds__(256, 1)
k1(const float* __restrict__ video,
   const float* __restrict__ wq, const float* __restrict__ bq,
   const float* __restrict__ wk, const float* __restrict__ bk,
   const float* __restrict__ wv, const float* __restrict__ bv,
   const float* __restrict__ ln_g, const float* __restrict__ ln_b)
{
    extern __shared__ float sm[];
    float* sX    = sm;                   // 49*512 raw vf, becomes vf+out
    float* sO    = sm + NP * VDIM;       // 49*512: q/k (stride 129), then avf
    float* sAttn = sO + NP * VDIM;       // 49*52

    const int tid  = threadIdx.x;
    const int item = blockIdx.x;
    const float* vf = video + (size_t)item * NP * VDIM;

    for (int i = tid; i < NP * VDIM / 4; i += 256)
        ((float4*)sX)[i] = ((const float4*)vf)[i];
    __syncthreads();

    // ---- q, k : thread owns one output column j (q: tid<128, k: tid>=128) ----
    {
        const int j = tid & 127;
        const float* W = (tid < 128) ? wq : wk;
        const float  b = (tid < 128) ? bq[j] : bk[j];
        float acc[NP];
#pragma unroll
        for (int n = 0; n < NP; n++) acc[n] = 0.f;
        const float4* wrow = (const float4*)(W + (size_t)j * VDIM);
        for (int c4 = 0; c4 < VDIM / 4; c4++){
            float4 w = wrow[c4];
#pragma unroll
            for (int n = 0; n < NP; n++){
                float4 x = ((const float4*)(sX + n * VDIM))[c4];
                acc[n] = fmaf(x.x, w.x, fmaf(x.y, w.y, fmaf(x.z, w.z, fmaf(x.w, w.w, acc[n]))));
            }
        }
        float* dst = sO + ((tid < 128) ? 0 : NP * 129);
#pragma unroll
        for (int n = 0; n < NP; n++) dst[n * 129 + j] = acc[n] + b;
    }
    __syncthreads();

    // ---- attn = softmax(q k^T), one warp per row n ----
    {
        const int w = tid >> 5, l = tid & 31;
        const float* sQ = sO;
        const float* sK = sO + NP * 129;
        for (int n = w; n < NP; n += 8){
            float a0 = 0.f, a1 = 0.f;
            const int m1  = l + 32;
            const int m1c = (m1 < NP) ? m1 : 0;
            for (int j = 0; j < QDIM; j++){
                float q = sQ[n * 129 + j];
                a0 = fmaf(q, sK[l   * 129 + j], a0);
                a1 = fmaf(q, sK[m1c * 129 + j], a1);
            }
            float v1 = (m1 < NP) ? a1 : -1e30f;
            float mx = wmax(fmaxf(a0, v1));
            float e0 = expf(a0 - mx);
            float e1 = (m1 < NP) ? expf(a1 - mx) : 0.f;
            float s  = wsum(e0 + e1);
            float inv = 1.f / s;
            sAttn[n * 52 + l] = e0 * inv;
            if (m1 < NP) sAttn[n * 52 + m1] = e1 * inv;
        }
    }
    __syncthreads();

    // ---- avf = attn @ X  -> sO (q/k dead) ----
    for (int p = 0; p < 2; p++){
        const int c = tid + p * 256;
        float acc[NP];
#pragma unroll
        for (int n = 0; n < NP; n++) acc[n] = 0.f;
        for (int m = 0; m < NP; m++){
            float x = sX[m * VDIM + c];
#pragma unroll
            for (int n = 0; n < NP; n++) acc[n] = fmaf(sAttn[n * 52 + m], x, acc[n]);
        }
#pragma unroll
        for (int n = 0; n < NP; n++) sO[n * VDIM + c] = acc[n];
    }
    __syncthreads();

    // ---- out = avf @ wv^T + bv (rows of attn sum to 1, so bias is exact);
    //      X += out (residual, in place) ----
    for (int p = 0; p < 2; p++){
        const int j = tid + p * 256;
        float acc[NP];
#pragma unroll
        for (int n = 0; n < NP; n++) acc[n] = 0.f;
        const float4* wrow = (const float4*)(wv + (size_t)j * VDIM);
        for (int c4 = 0; c4 < VDIM / 4; c4++){
            float4 w = wrow[c4];
#pragma unroll
            for (int n = 0; n < NP; n++){
                float4 x = ((const float4*)(sO + n * VDIM))[c4];
                acc[n] = fmaf(x.x, w.x, fmaf(x.y, w.y, fmaf(x.z, w.z, fmaf(x.w, w.w, acc[n]))));
            }
        }
        float b = bv[j];
#pragma unroll
        for (int n = 0; n < NP; n++) sX[n * VDIM + j] += acc[n] + b;
    }
    __syncthreads();

    // ---- LayerNorm rows -> g_vf2 ----
    {
        const int w = tid >> 5, l = tid & 31;
        float* gout = g_vf2 + (size_t)item * NP * VDIM;
        for (int n = w; n < NP; n += 8){
            float s = 0.f, s2 = 0.f;
            for (int j = l; j < VDIM; j += 32){
                float v = sX[n * VDIM + j];
                s += v; s2 = fmaf(v, v, s2);
            }
            s = wsum(s); s2 = wsum(s2);
            float mu  = s * (1.f / VDIM);
            float var = s2 * (1.f / VDIM) - mu * mu;
            float rs  = rsqrtf(var + 1e-5f);
            for (int j = l; j < VDIM; j += 32)
                gout[n * VDIM + j] = (sX[n * VDIM + j] - mu) * rs * ln_g[j] + ln_b[j];
        }
    }
}

// ---------------------------------------------------------------------------
// Kernel 2: all remaining branches, fully fused per item
// ---------------------------------------------------------------------------
__global__ void __launch_bounds__(256, 1)
k2(const float* __restrict__ video, const float* __restrict__ audio,
   const float* __restrict__ w_ave, const float* __restrict__ b_ave,
   const float* __restrict__ w_v3, const float* __restrict__ b_v3,
   const float* __restrict__ w_avatt, const float* __restrict__ b_avatt,
   const float* __restrict__ w_a1, const float* __restrict__ b_a1,
   const float* __restrict__ w_v1, const float* __restrict__ b_v1,
   const float* __restrict__ w_bn, const float* __restrict__ b_bn,
   const float* __restrict__ w_ca, const float* __restrict__ b_ca,
   const float* __restrict__ w_v2, const float* __restrict__ b_v2,
   const float* __restrict__ w_a2, const float* __restrict__ b_a2,
   const float* __restrict__ w_sa, const float* __restrict__ b_sa,
   float* __restrict__ out)
{
    extern __shared__ float sm[];
    float* sV   = sm;                  // 49*512 vf2
    float* sR   = sm + NP * VDIM;      // 49*512 raw vf -> c_att (in place)
    float* colm = sm + 2 * NP * VDIM;  // 512
    float* aq1  = colm + 512;          // 512
    float* ch   = aq1 + 512;           // 512
    float* colv = ch + 512;            // 512
    float* havg = colv + 512;          // 256
    float* aq2  = havg + 256;          // 256
    float* avqv = aq2 + 256;           // 256
    float* aud  = avqv + 256;          // 128
    float* sSelf= aud + 128;           // 64
    float* sSp  = sSelf + 64;          // 64

    const int tid  = threadIdx.x;
    const int item = blockIdx.x;
    const int bb = item / NT, tt = item % NT;

    const float4* gv2 = (const float4*)(g_vf2 + (size_t)item * NP * VDIM);
    const float4* grw = (const float4*)(video + (size_t)item * NP * VDIM);
    for (int i = tid; i < NP * VDIM / 4; i += 256){
        ((float4*)sV)[i] = gv2[i];
        ((float4*)sR)[i] = grw[i];
    }
    const float* ap = audio + ((size_t)tt * NB + bb) * ADIM;   // audio[T,B,AD] -> [b,t]
    if (tid < 32) ((float4*)aud)[tid] = ((const float4*)ap)[tid];
    if (tid < NP){ sSelf[tid] = b_avatt[0]; sSp[tid] = b_sa[0]; }
    __syncthreads();

    // ---- P1: column mean of vf2, aq1 = relu(W_a1 aud), aq2 = relu(W_a2 aud) ----
    for (int p = 0; p < 2; p++){
        int c = tid + p * 256;
        float s = 0.f;
        for (int n = 0; n < NP; n++) s += sV[n * VDIM + c];
        colm[c] = s * (1.f / NP);
        const float4* wr = (const float4*)(w_a1 + (size_t)c * ADIM);
        float a = 0.f;
        for (int k = 0; k < ADIM / 4; k++){
            float4 w = wr[k]; float4 x = ((const float4*)aud)[k];
            a = fmaf(w.x, x.x, fmaf(w.y, x.y, fmaf(w.z, x.z, fmaf(w.w, x.w, a))));
        }
        aq1[c] = fmaxf(a + b_a1[c], 0.f);
    }
    {
        const float4* wr = (const float4*)(w_a2 + (size_t)tid * ADIM);
        float a = 0.f;
        for (int k = 0; k < ADIM / 4; k++){
            float4 w = wr[k]; float4 x = ((const float4*)aud)[k];
            a = fmaf(w.x, x.x, fmaf(w.y, x.y, fmaf(w.z, x.z, fmaf(w.w, x.w, a))));
        }
        aq2[tid] = fmaxf(a + b_a2[tid], 0.f);
    }
    __syncthreads();

    // ---- P2: havg = relu(W_ave colm) ----
    {
        const float4* wr = (const float4*)(w_ave + (size_t)tid * VDIM);
        float a = 0.f;
        for (int k = 0; k < VDIM / 4; k++){
            float4 w = wr[k]; float4 x = ((const float4*)colm)[k];
            a = fmaf(w.x, x.x, fmaf(w.y, x.y, fmaf(w.z, x.z, fmaf(w.w, x.w, a))));
        }
        havg[tid] = fmaxf(a + b_ave[tid], 0.f);
    }
    __syncthreads();

    // ---- P3a: self branch GEMM (w_v3), fused into self-attn logits ----
    {
        const int j = tid;                       // HD == 256 == blockDim
        float acc[NP];
#pragma unroll
        for (int n = 0; n < NP; n++) acc[n] = 0.f;
        const float4* wrow = (const float4*)(w_v3 + (size_t)j * VDIM);
        for (int c4 = 0; c4 < VDIM / 4; c4++){
            float4 w = wrow[c4];
#pragma unroll
            for (int n = 0; n < NP; n++){
                float4 x = ((const float4*)(sV + n * VDIM))[c4];
                acc[n] = fmaf(x.x, w.x, fmaf(x.y, w.y, fmaf(x.z, w.z, fmaf(x.w, w.w, acc[n]))));
            }
        }
        const float bj = b_v3[j];
        const float scale = havg[j] * w_avatt[j];
#pragma unroll
        for (int n = 0; n < NP; n++){
            float v = fmaxf(acc[n] + bj, 0.f) * scale;
            v = wsum(v);
            if ((tid & 31) == 0) atomicAdd(&sSelf[n], v);
        }
    }
    // ---- P3b: vq1 GEMM (w_v1), fused column mean -> colv = aq1 * mean_n relu(.) ----
    for (int p = 0; p < 2; p++){
        const int c = tid + p * 256;
        float acc[NP];
#pragma unroll
        for (int n = 0; n < NP; n++) acc[n] = 0.f;
        const float4* wrow = (const float4*)(w_v1 + (size_t)c * VDIM);
        for (int c4 = 0; c4 < VDIM / 4; c4++){
            float4 w = wrow[c4];
#pragma unroll
            for (int n = 0; n < NP; n++){
                float4 x = ((const float4*)(sV + n * VDIM))[c4];
                acc[n] = fmaf(x.x, w.x, fmaf(x.y, w.y, fmaf(x.z, w.z, fmaf(x.w, w.w, acc[n]))));
            }
        }
        const float bc = b_v1[c];
        float s = 0.f;
#pragma unroll
        for (int n = 0; n < NP; n++) s += fmaxf(acc[n] + bc, 0.f);
        colv[c] = s * (1.f / NP) * aq1[c];
    }
    __syncthreads();

    // ---- P4: avq = relu(W_bn colv); warp0: self_maps = softmax(tanh(logits)) ----
    {
        const float4* wr = (const float4*)(w_bn + (size_t)tid * VDIM);
        float a = 0.f;
        for (int k = 0; k < VDIM / 4; k++){
            float4 w = wr[k]; float4 x = ((const float4*)colv)[k];
            a = fmaf(w.x, x.x, fmaf(w.y, x.y, fmaf(w.z, x.z, fmaf(w.w, x.w, a))));
        }
        avqv[tid] = fmaxf(a + b_bn[tid], 0.f);
    }
    if (tid < 32){
        float v0 = tanhf(sSelf[tid]);
        float v1 = (tid + 32 < NP) ? tanhf(sSelf[tid + 32]) : -1e30f;
        float mx = wmax(fmaxf(v0, v1));
        float e0 = expf(v0 - mx);
        float e1 = (tid + 32 < NP) ? expf(v1 - mx) : 0.f;
        float s  = wsum(e0 + e1);
        sSelf[tid] = e0 / s;
        if (tid + 32 < NP) sSelf[tid + 32] = e1 / s;
    }
    __syncthreads();

    // ---- P5: ch = sigmoid(W_ca avq) + 1 ----
    for (int p = 0; p < 2; p++){
        int c = tid + p * 256;
        const float4* wr = (const float4*)(w_ca + (size_t)c * HDIM);
        float a = 0.f;
        for (int k = 0; k < HDIM / 4; k++){
            float4 w = wr[k]; float4 x = ((const float4*)avqv)[k];
            a = fmaf(w.x, x.x, fmaf(w.y, x.y, fmaf(w.z, x.z, fmaf(w.w, x.w, a))));
        }
        ch[c] = 1.f + 1.f / (1.f + expf(-(a + b_ca[c])));
    }
    __syncthreads();

    // ---- P6: c_att = raw * ch, in place over sR ----
    for (int i = tid; i < NP * VDIM / 4; i += 256){
        int c4i = i & 127;
        float4 r = ((float4*)sR)[i];
        float4 m = ((const float4*)ch)[c4i];
        r.x *= m.x; r.y *= m.y; r.z *= m.z; r.w *= m.w;
        ((float4*)sR)[i] = r;
    }
    __syncthreads();

    // ---- P7: cq GEMM (w_v2) fused into spatial-attn logits ----
    {
        const int j = tid;
        float acc[NP];
#pragma unroll
        for (int n = 0; n < NP; n++) acc[n] = 0.f;
        const float4* wrow = (const float4*)(w_v2 + (size_t)j * VDIM);
        for (int c4 = 0; c4 < VDIM / 4; c4++){
            float4 w = wrow[c4];
#pragma unroll
            for (int n = 0; n < NP; n++){
                float4 x = ((const float4*)(sR + n * VDIM))[c4];
                acc[n] = fmaf(x.x, w.x, fmaf(x.y, w.y, fmaf(x.z, w.z, fmaf(x.w, w.w, acc[n]))));
            }
        }
        const float bj = b_v2[j];
        const float scale = aq2[j] * w_sa[j];
#pragma unroll
        for (int n = 0; n < NP; n++){
            float v = fmaxf(acc[n] + bj, 0.f) * scale;
            v = wsum(v);
            if ((tid & 31) == 0) atomicAdd(&sSp[n], v);
        }
    }
    __syncthreads();

    // ---- P8: sp_maps = softmax(tanh(logits)) ----
    if (tid < 32){
        float v0 = tanhf(sSp[tid]);
        float v1 = (tid + 32 < NP) ? tanhf(sSp[tid + 32]) : -1e30f;
        float mx = wmax(fmaxf(v0, v1));
        float e0 = expf(v0 - mx);
        float e1 = (tid + 32 < NP) ? expf(v1 - mx) : 0.f;
        float s  = wsum(e0 + e1);
        sSp[tid] = e0 / s;
        if (tid + 32 < NP) sSp[tid + 32] = e1 / s;
    }
    __syncthreads();

    // ---- P9: outputs ----
    for (int p = 0; p < 2; p++){
        int c = tid + p * 256;
        float sa = 0.f, cs = 0.f;
        for (int n = 0; n < NP; n++){
            sa = fmaf(sSelf[n], sV[n * VDIM + c], sa);
            cs = fmaf(sSp[n],   sR[n * VDIM + c], cs);
        }
        float g = 1.f + 0.5f / (1.f + expf(-sa));
        out[(size_t)item * VDIM + c] = cs * g;
    }
    if (tid < ADIM)
        out[(size_t)BT * VDIM + (size_t)item * ADIM + tid] = aud[tid];
}

// ---------------------------------------------------------------------------
extern "C" void kernel_launch(void* const* d_in, const int* in_sizes, int n_in,
                              void* d_out, int out_size)
{
    const float* video = (const float*)d_in[0];
    const float* audio = (const float*)d_in[1];
    const float* wq    = (const float*)d_in[2];  const float* bq    = (const float*)d_in[3];
    const float* wk    = (const float*)d_in[4];  const float* bk    = (const float*)d_in[5];
    const float* wv    = (const float*)d_in[6];  const float* bv    = (const float*)d_in[7];
    const float* ln_g  = (const float*)d_in[8];  const float* ln_b  = (const float*)d_in[9];
    const float* w_ave = (const float*)d_in[10]; const float* b_ave = (const float*)d_in[11];
    const float* w_v3  = (const float*)d_in[12]; const float* b_v3  = (const float*)d_in[13];
    const float* w_avt = (const float*)d_in[14]; const float* b_avt = (const float*)d_in[15];
    const float* w_a1  = (const float*)d_in[16]; const float* b_a1  = (const float*)d_in[17];
    const float* w_v1  = (const float*)d_in[18]; const float* b_v1  = (const float*)d_in[19];
    const float* w_bn  = (const float*)d_in[20]; const float* b_bn  = (const float*)d_in[21];
    const float* w_ca  = (const float*)d_in[22]; const float* b_ca  = (const float*)d_in[23];
    const float* w_v2  = (const float*)d_in[24]; const float* b_v2  = (const float*)d_in[25];
    const float* w_a2  = (const float*)d_in[26]; const float* b_a2  = (const float*)d_in[27];
    const float* w_sa  = (const float*)d_in[28]; const float* b_sa  = (const float*)d_in[29];
    float* out = (float*)d_out;

    const int smem1 = (NP * VDIM * 2 + NP * 52) * (int)sizeof(float);   // ~211 KB
    const int smem2 = (NP * VDIM * 2 + 3072) * (int)sizeof(float);      // ~213 KB
    cudaFuncSetAttribute(k1, cudaFuncAttributeMaxDynamicSharedMemorySize, smem1);
    cudaFuncSetAttribute(k2, cudaFuncAttributeMaxDynamicSharedMemorySize, smem2);

    k1<<<BT, 256, smem1>>>(video, wq, bq, wk, bk, wv, bv, ln_g, ln_b);
    k2<<<BT, 256, smem2>>>(video, audio, w_ave, b_ave, w_v3, b_v3, w_avt, b_avt,
                           w_a1, b_a1, w_v1, b_v1, w_bn, b_bn, w_ca, b_ca,
                           w_v2, b_v2, w_a2, b_a2, w_sa, b_sa, out);
}